// round 5
// baseline (speedup 1.0000x reference)
#include <cuda_runtime.h>

// CausalAttention: out = softmax_causal((xWq)(xWk)^T / sqrt(1024)) (xWv)
// b=4, s=2048, d_in=d_out=1024, fp32.
//
// Plan: 4 graph-capturable kernels, fp32 throughout (rel-err safety), with
// packed fma.rn.f32x2 (FFMA2) inner loops for 2x fp32 throughput.
//   1) qkv_kernel   : Q/K/V = x @ W{q,k,v}           (grid.z selects W)
//   2) score_kernel : S = Q K^T * 1/32, causal block skip (kb<=qb only)
//   3) softmax_kernel: row softmax over S[0..q], zero-fill (q, tile_end)
//   4) out_kernel   : out = P @ V with per-q-tile K limit
// Scratch in __device__ globals (no allocation anywhere).

#define BM 128
#define BN 128
#define BK 8
#define TPB 256

typedef unsigned long long ull;

// ---------------- scratch ----------------
__device__ float g_Q[4 * 2048 * 1024];
__device__ float g_K[4 * 2048 * 1024];
__device__ float g_V[4 * 2048 * 1024];
__device__ float g_S[(size_t)4 * 2048 * 2048];

// ---------------- packed f32x2 helpers ----------------
__device__ __forceinline__ ull pack_dup(float a) {
    ull r;
    asm("mov.b64 %0, {%1, %1};" : "=l"(r) : "f"(a));
    return r;
}
__device__ __forceinline__ void fma2(ull& c, ull a, ull b) {
    asm("fma.rn.f32x2 %0, %1, %2, %0;" : "+l"(c) : "l"(a), "l"(b));
}
__device__ __forceinline__ float2 unpack2(ull v) {
    float2 r;
    asm("mov.b64 {%0, %1}, %2;" : "=f"(r.x), "=f"(r.y) : "l"(v));
    return r;
}

// ---------------- GEMM body (128x128x8 tile, 256 thr, 8x8/thread) ----------------
// A: row-major [M, lda-K-contig], loaded transposed into As[k][m].
// B (BT=false): row-major [K, N], loaded straight into Bs[k][n].
// B (BT=true) : row-major [N, ldb-K-contig] (i.e. we need B^T), loaded
//               transposed into Bs[k][n] with the same mapping as A.
template <bool BT>
__device__ __forceinline__ void gemm_body(const float* __restrict__ A, int lda,
                                          const float* __restrict__ B, int ldb,
                                          int m0, int n0, int Klen,
                                          ull acc[8][4], int ty4, int tx4) {
    __shared__ float As[BK][BM];
    __shared__ float Bs[BK][BN];

    const int tid  = threadIdx.x;
    const int arow = tid >> 1;         // 0..127
    const int ak   = (tid & 1) * 4;    // 0 or 4
    const int brow = tid >> 5;         // 0..7
    const int bcol = (tid & 31) * 4;   // 0..124

    const float* Ab = A + (size_t)(m0 + arow) * lda + ak;
    const float* Bb;
    if (BT) Bb = B + (size_t)(n0 + arow) * ldb + ak;
    else    Bb = B + (size_t)brow * ldb + n0 + bcol;

    float4 ra = *(const float4*)(Ab);
    float4 rb = *(const float4*)(Bb);

    for (int k0 = 0; k0 < Klen; k0 += BK) {
        // stage current fragments into smem
        As[ak + 0][arow] = ra.x;
        As[ak + 1][arow] = ra.y;
        As[ak + 2][arow] = ra.z;
        As[ak + 3][arow] = ra.w;
        if (BT) {
            Bs[ak + 0][arow] = rb.x;
            Bs[ak + 1][arow] = rb.y;
            Bs[ak + 2][arow] = rb.z;
            Bs[ak + 3][arow] = rb.w;
        } else {
            *(float4*)&Bs[brow][bcol] = rb;
        }
        __syncthreads();

        // prefetch next tile into registers (hide L2/DRAM behind compute)
        const int kn = k0 + BK;
        if (kn < Klen) {
            ra = *(const float4*)(Ab + kn);
            if (BT) rb = *(const float4*)(Bb + kn);
            else    rb = *(const float4*)(Bb + (size_t)kn * ldb);
        }

#pragma unroll
        for (int kk = 0; kk < BK; ++kk) {
            float4 a0 = *(const float4*)&As[kk][ty4];
            float4 a1 = *(const float4*)&As[kk][64 + ty4];
            ulonglong2 b0 = *(const ulonglong2*)&Bs[kk][tx4];
            ulonglong2 b1 = *(const ulonglong2*)&Bs[kk][64 + tx4];
            float av[8] = {a0.x, a0.y, a0.z, a0.w, a1.x, a1.y, a1.z, a1.w};
            ull bp0 = b0.x, bp1 = b0.y, bp2 = b1.x, bp3 = b1.y;
#pragma unroll
            for (int i = 0; i < 8; ++i) {
                ull ad = pack_dup(av[i]);
                fma2(acc[i][0], ad, bp0);
                fma2(acc[i][1], ad, bp1);
                fma2(acc[i][2], ad, bp2);
                fma2(acc[i][3], ad, bp3);
            }
        }
        __syncthreads();
    }
}

__device__ __forceinline__ void store_tile(float* __restrict__ C, int ldc,
                                           int m0, int n0, ull acc[8][4],
                                           int ty4, int tx4, float scale) {
#pragma unroll
    for (int i = 0; i < 8; ++i) {
        const int r = m0 + ((i < 4) ? (ty4 + i) : (64 + ty4 + i - 4));
#pragma unroll
        for (int j = 0; j < 4; ++j) {
            const int c = n0 + ((j < 2) ? (tx4 + 2 * j) : (64 + tx4 + 2 * (j - 2)));
            float2 v = unpack2(acc[i][j]);
            v.x *= scale;
            v.y *= scale;
            *(float2*)&C[(size_t)r * ldc + c] = v;
        }
    }
}

// ---------------- kernel 1: QKV projections ----------------
__global__ void __launch_bounds__(TPB, 2)
qkv_kernel(const float* __restrict__ x, const float* __restrict__ Wq,
           const float* __restrict__ Wk, const float* __restrict__ Wv) {
    const float* B;
    float* C;
    if (blockIdx.z == 0)      { B = Wq; C = g_Q; }
    else if (blockIdx.z == 1) { B = Wk; C = g_K; }
    else                      { B = Wv; C = g_V; }

    const int m0 = blockIdx.y * BM;   // over 8192 rows (b*s)
    const int n0 = blockIdx.x * BN;   // over 1024 cols
    const int tid = threadIdx.x;
    const int tx4 = (tid & 15) * 4;
    const int ty4 = (tid >> 4) * 4;

    ull acc[8][4];
#pragma unroll
    for (int i = 0; i < 8; ++i)
#pragma unroll
        for (int j = 0; j < 4; ++j) acc[i][j] = 0ULL;

    gemm_body<false>(x, 1024, B, 1024, m0, n0, 1024, acc, ty4, tx4);
    store_tile(C, 1024, m0, n0, acc, ty4, tx4, 1.0f);
}

// ---------------- kernel 2: S = Q K^T * 1/32 (causal block skip) ----------------
__global__ void __launch_bounds__(TPB, 2)
score_kernel() {
    const int kb = blockIdx.x;
    const int qb = blockIdx.y;
    const int b  = blockIdx.z;
    if (kb > qb) return;  // block entirely above diagonal: never read downstream

    const float* Q  = g_Q + (size_t)b * 2048 * 1024;
    const float* Km = g_K + (size_t)b * 2048 * 1024;
    float*       S  = g_S + (size_t)b * 2048 * 2048;

    const int tid = threadIdx.x;
    const int tx4 = (tid & 15) * 4;
    const int ty4 = (tid >> 4) * 4;

    ull acc[8][4];
#pragma unroll
    for (int i = 0; i < 8; ++i)
#pragma unroll
        for (int j = 0; j < 4; ++j) acc[i][j] = 0ULL;

    gemm_body<true>(Q, 1024, Km, 1024, qb * BM, kb * BN, 1024, acc, ty4, tx4);
    store_tile(S, 2048, qb * BM, kb * BN, acc, ty4, tx4, 0.03125f /* 1/sqrt(1024) */);
}

// ---------------- kernel 3: causal row softmax (in place) ----------------
__global__ void softmax_kernel() {
    const int q = blockIdx.x;  // 0..2047
    const int b = blockIdx.y;  // 0..3
    float* row = g_S + ((size_t)b * 2048 + q) * 2048;
    const int len = q + 1;
    const int tid = threadIdx.x;

    __shared__ float red[TPB];

    // 1) row max over valid entries
    float m = -1e30f;
    for (int i = tid; i < len; i += TPB) m = fmaxf(m, row[i]);
    red[tid] = m;
    __syncthreads();
#pragma unroll
    for (int s = TPB / 2; s > 0; s >>= 1) {
        if (tid < s) red[tid] = fmaxf(red[tid], red[tid + s]);
        __syncthreads();
    }
    m = red[0];
    __syncthreads();

    // 2) exp + sum
    float sum = 0.0f;
    for (int i = tid; i < len; i += TPB) {
        float e = __expf(row[i] - m);
        row[i] = e;
        sum += e;
    }
    red[tid] = sum;
    __syncthreads();
#pragma unroll
    for (int s = TPB / 2; s > 0; s >>= 1) {
        if (tid < s) red[tid] += red[tid + s];
        __syncthreads();
    }
    const float inv = 1.0f / red[0];
    __syncthreads();

    // 3) normalize + zero the masked tail up to the 128-tile boundary so the
    //    PV GEMM can read full tiles without masking.
    for (int i = tid; i < len; i += TPB) row[i] *= inv;
    const int klim = ((q >> 7) + 1) << 7;  // <= 2048
    for (int i = len + tid; i < klim; i += TPB) row[i] = 0.0f;
}

// ---------------- kernel 4: out = P @ V (K limited by causality) ----------------
__global__ void __launch_bounds__(TPB, 2)
out_kernel(float* __restrict__ out) {
    const int nb = blockIdx.x;  // 0..7  (1024 output cols)
    const int qb = blockIdx.y;  // 0..15 (2048 q rows)
    const int b  = blockIdx.z;

    const float* P = g_S + (size_t)b * 2048 * 2048;
    const float* V = g_V + (size_t)b * 2048 * 1024;
    float*       C = out + (size_t)b * 2048 * 1024;

    const int tid = threadIdx.x;
    const int tx4 = (tid & 15) * 4;
    const int ty4 = (tid >> 4) * 4;
    const int Klen = (qb + 1) * BM;  // causal: keys beyond this tile are zero/unused

    ull acc[8][4];
#pragma unroll
    for (int i = 0; i < 8; ++i)
#pragma unroll
        for (int j = 0; j < 4; ++j) acc[i][j] = 0ULL;

    gemm_body<false>(P, 2048, V, 1024, qb * BM, nb * BN, Klen, acc, ty4, tx4);
    store_tile(C, 1024, qb * BM, nb * BN, acc, ty4, tx4, 1.0f);
}

// ---------------- launch ----------------
extern "C" void kernel_launch(void* const* d_in, const int* in_sizes, int n_in,
                              void* d_out, int out_size) {
    const float* x  = (const float*)d_in[0];
    const float* Wq = (const float*)d_in[1];
    const float* Wk = (const float*)d_in[2];
    const float* Wv = (const float*)d_in[3];
    float* out = (float*)d_out;

    dim3 g1(1024 / BN, 8192 / BM, 3);   // (8, 64, 3)
    qkv_kernel<<<g1, TPB>>>(x, Wq, Wk, Wv);

    dim3 g2(16, 16, 4);                 // (kb, qb, batch), kb>qb early-out
    score_kernel<<<g2, TPB>>>();

    dim3 g3(2048, 4);                   // (q, batch)
    softmax_kernel<<<g3, TPB>>>();

    dim3 g4(1024 / BN, 2048 / BM, 4);   // (8, 16, 4)
    out_kernel<<<g4, TPB>>>(out);
}

// round 9
// speedup vs baseline: 1.9894x; 1.9894x over previous
#include <cuda_runtime.h>
#include <cuda_bf16.h>
#include <cstdint>

// CausalAttention via mma.sync bf16 hi/lo-split (3-MMA emulated fp32).
// tcgen05 is rejected by this harness's ptxas target (sm_103 baseline), so we
// use the sm_80 tensor-core ISA: mma.sync.m16n8k16 + ldmatrix + cp.async.
//
//  1) split_x    : x  -> xh, xl (bf16)
//  2) wt_kernel  : W{q,k,v} -> transposed hi/lo bf16 (W^T, K-contiguous)
//  3) proj_kernel: Q,K (split bf16 epilogue) and V (fp32) = x @ W
//  4) vt_kernel  : V -> V^T hi/lo bf16
//  5) score_kern : S = Q K^T / 32  (causal block skip), fp32
//  6) softmax    : row softmax -> Ph, Pl (bf16), zero tail to 128-boundary
//  7) pv_kernel  : out = P @ V  (fp32 epilogue, causal K limit)

typedef unsigned int u32;
typedef unsigned long long u64;

#define TPB 256
#define BK 64                 // K-chunk in bf16 elems
#define LDSS 72               // padded smem row (72 elems = 144B, conflict-free ldmatrix)
#define TILE_B (128 * LDSS * 2)          // 18432 B per 128x64 tile
#define BUF_B (4 * TILE_B)               // Ah, Al, Bh, Bl
#define GEMM_SMEM (2 * BUF_B)            // double buffer = 147456 B

// ---------------- scratch (no allocation anywhere) ----------------
__device__ __nv_bfloat16 g_xh[8192 * 1024];
__device__ __nv_bfloat16 g_xl[8192 * 1024];
__device__ __nv_bfloat16 g_WTh[3 * 1024 * 1024];
__device__ __nv_bfloat16 g_WTl[3 * 1024 * 1024];
__device__ __nv_bfloat16 g_Qh[4 * 2048 * 1024];
__device__ __nv_bfloat16 g_Ql[4 * 2048 * 1024];
__device__ __nv_bfloat16 g_Kh[4 * 2048 * 1024];
__device__ __nv_bfloat16 g_Kl[4 * 2048 * 1024];
__device__ float         g_V[4 * 2048 * 1024];
__device__ __nv_bfloat16 g_VTh[(size_t)4 * 1024 * 2048];
__device__ __nv_bfloat16 g_VTl[(size_t)4 * 1024 * 2048];
__device__ float         g_S[(size_t)4 * 2048 * 2048];
__device__ __nv_bfloat16 g_Ph[(size_t)4 * 2048 * 2048];
__device__ __nv_bfloat16 g_Pl[(size_t)4 * 2048 * 2048];

// ---------------- helpers ----------------
__device__ __forceinline__ u32 smem_u32(const void* p) {
    u32 a;
    asm("{ .reg .u64 t; cvta.to.shared.u64 t, %1; cvt.u32.u64 %0, t; }"
        : "=r"(a) : "l"(p));
    return a;
}

__device__ __forceinline__ void cp_async16(u32 dst, const void* src) {
    asm volatile("cp.async.cg.shared.global [%0], [%1], 16;"
                 :: "r"(dst), "l"(src) : "memory");
}
#define CP_COMMIT() asm volatile("cp.async.commit_group;" ::: "memory")
#define CP_WAIT(N)  asm volatile("cp.async.wait_group %0;" :: "n"(N) : "memory")

__device__ __forceinline__ void ldmx4(u32 a, u32& r0, u32& r1, u32& r2, u32& r3) {
    asm volatile("ldmatrix.sync.aligned.m8n8.x4.shared.b16 {%0,%1,%2,%3}, [%4];"
                 : "=r"(r0), "=r"(r1), "=r"(r2), "=r"(r3) : "r"(a));
}

__device__ __forceinline__ void mma16816(float c[4], const u32 a[4], const u32 b[2]) {
    asm volatile(
        "mma.sync.aligned.m16n8k16.row.col.f32.bf16.bf16.f32 "
        "{%0,%1,%2,%3}, {%4,%5,%6,%7}, {%8,%9}, {%0,%1,%2,%3};"
        : "+f"(c[0]), "+f"(c[1]), "+f"(c[2]), "+f"(c[3])
        : "r"(a[0]), "r"(a[1]), "r"(a[2]), "r"(a[3]), "r"(b[0]), "r"(b[1]));
}

__device__ __forceinline__ void split2(float v, __nv_bfloat16& h, __nv_bfloat16& l) {
    h = __float2bfloat16_rn(v);
    l = __float2bfloat16_rn(v - __bfloat162float(h));
}

// ---------------- GEMM core ----------------
// C[128x128 tile at (m0,n0)] = sum_k A[m,k]*B[n,k], A/B hi+lo bf16, K-major.
// MODE 0: fp32 out (Cf) * scale.   MODE 1: split bf16 out (Ch, Cl).
template <int MODE>
__device__ __forceinline__ void gemm_core(
    const __nv_bfloat16* __restrict__ Ah, const __nv_bfloat16* __restrict__ Al, int lda,
    const __nv_bfloat16* __restrict__ Bh, const __nv_bfloat16* __restrict__ Bl, int ldb,
    int m0, int n0, int Klen, float scale,
    float* __restrict__ Cf, __nv_bfloat16* __restrict__ Ch, __nv_bfloat16* __restrict__ Cl,
    int ldc)
{
    extern __shared__ char smem[];
    const u32 sbase = smem_u32(smem);
    const int tid = threadIdx.x;
    const int wid = tid >> 5;
    const int lane = tid & 31;
    const int warp_m = (wid & 3) * 32;   // 4 warps over M
    const int warp_n = (wid >> 2) * 64;  // 2 warps over N

    // cp.async mapping: 32 rows x 8 segs(16B) per pass, 4 passes per tile
    const int lrow = tid >> 3;            // 0..31
    const int lseg = (tid & 7) * 8;       // elem col 0..56
    const u32 dst_off = (u32)(lrow * LDSS + lseg) * 2;
    const __nv_bfloat16* pAh = Ah + (size_t)(m0 + lrow) * lda + lseg;
    const __nv_bfloat16* pAl = Al + (size_t)(m0 + lrow) * lda + lseg;
    const __nv_bfloat16* pBh = Bh + (size_t)(n0 + lrow) * ldb + lseg;
    const __nv_bfloat16* pBl = Bl + (size_t)(n0 + lrow) * ldb + lseg;

    const int nch = Klen / BK;

    // ldmatrix base offsets (within a tile)
    const u32 lm_a0 = (u32)((warp_m + (lane & 15)) * LDSS + (lane >> 4) * 8) * 2;
    const u32 lm_b0 = (u32)((warp_n + (lane & 15)) * LDSS + (lane >> 4) * 8) * 2;

    float acc[2][8][4];
#pragma unroll
    for (int i = 0; i < 2; ++i)
#pragma unroll
        for (int j = 0; j < 8; ++j)
#pragma unroll
            for (int q = 0; q < 4; ++q) acc[i][j][q] = 0.0f;

    // ---- prologue: load chunk 0 ----
    {
        const u32 ba = sbase;  // buffer 0
#pragma unroll
        for (int p = 0; p < 4; ++p) {
            const u32 d = ba + dst_off + (u32)(32 * p * LDSS) * 2;
            cp_async16(d + 0 * TILE_B, pAh + (size_t)(32 * p) * lda);
            cp_async16(d + 1 * TILE_B, pAl + (size_t)(32 * p) * lda);
            cp_async16(d + 2 * TILE_B, pBh + (size_t)(32 * p) * ldb);
            cp_async16(d + 3 * TILE_B, pBl + (size_t)(32 * p) * ldb);
        }
        CP_COMMIT();
    }

    for (int c = 0; c < nch; ++c) {
        // issue loads for chunk c+1 into the other buffer
        if (c + 1 < nch) {
            const u32 ba = sbase + ((c + 1) & 1) * BUF_B;
            const int k0 = (c + 1) * BK;
#pragma unroll
            for (int p = 0; p < 4; ++p) {
                const u32 d = ba + dst_off + (u32)(32 * p * LDSS) * 2;
                cp_async16(d + 0 * TILE_B, pAh + (size_t)(32 * p) * lda + k0);
                cp_async16(d + 1 * TILE_B, pAl + (size_t)(32 * p) * lda + k0);
                cp_async16(d + 2 * TILE_B, pBh + (size_t)(32 * p) * ldb + k0);
                cp_async16(d + 3 * TILE_B, pBl + (size_t)(32 * p) * ldb + k0);
            }
            CP_COMMIT();
            CP_WAIT(1);   // chunk c complete, c+1 in flight
        } else {
            CP_WAIT(0);
        }
        __syncthreads();

        const u32 ba = sbase + (c & 1) * BUF_B;
        const u32 aAh = ba + lm_a0;
        const u32 aAl = ba + TILE_B + lm_a0;
        const u32 aBh = ba + 2 * TILE_B + lm_b0;
        const u32 aBl = ba + 3 * TILE_B + lm_b0;

#pragma unroll
        for (int ks = 0; ks < BK / 16; ++ks) {
            const u32 ko = (u32)(ks * 16) * 2;
            u32 ah[2][4], al[2][4], bh[8][2], bl[8][2];
#pragma unroll
            for (int mf = 0; mf < 2; ++mf) {
                ldmx4(aAh + ko + (u32)(mf * 16 * LDSS) * 2,
                      ah[mf][0], ah[mf][1], ah[mf][2], ah[mf][3]);
                ldmx4(aAl + ko + (u32)(mf * 16 * LDSS) * 2,
                      al[mf][0], al[mf][1], al[mf][2], al[mf][3]);
            }
#pragma unroll
            for (int g = 0; g < 4; ++g) {   // 16 n-rows per ldmatrix.x4
                u32 r0, r1, r2, r3;
                ldmx4(aBh + ko + (u32)(g * 16 * LDSS) * 2, r0, r1, r2, r3);
                bh[2 * g][0] = r0; bh[2 * g][1] = r2;
                bh[2 * g + 1][0] = r1; bh[2 * g + 1][1] = r3;
                ldmx4(aBl + ko + (u32)(g * 16 * LDSS) * 2, r0, r1, r2, r3);
                bl[2 * g][0] = r0; bl[2 * g][1] = r2;
                bl[2 * g + 1][0] = r1; bl[2 * g + 1][1] = r3;
            }
#pragma unroll
            for (int mf = 0; mf < 2; ++mf)
#pragma unroll
                for (int nf = 0; nf < 8; ++nf) {
                    mma16816(acc[mf][nf], ah[mf], bh[nf]);
                    mma16816(acc[mf][nf], ah[mf], bl[nf]);
                    mma16816(acc[mf][nf], al[mf], bh[nf]);
                }
        }
        __syncthreads();
    }

    // ---- epilogue ----
    const int erow = lane >> 2;
    const int ecol = (lane & 3) * 2;
#pragma unroll
    for (int mf = 0; mf < 2; ++mf) {
        const int rbase = m0 + warp_m + mf * 16 + erow;
#pragma unroll
        for (int nf = 0; nf < 8; ++nf) {
            const int ccol = n0 + warp_n + nf * 8 + ecol;
            if (MODE == 0) {
                float2 v0, v1;
                v0.x = acc[mf][nf][0] * scale; v0.y = acc[mf][nf][1] * scale;
                v1.x = acc[mf][nf][2] * scale; v1.y = acc[mf][nf][3] * scale;
                *(float2*)(Cf + (size_t)rbase * ldc + ccol) = v0;
                *(float2*)(Cf + (size_t)(rbase + 8) * ldc + ccol) = v1;
            } else {
                __nv_bfloat16 h0, l0, h1, l1;
                split2(acc[mf][nf][0], h0, l0);
                split2(acc[mf][nf][1], h1, l1);
                *(__nv_bfloat162*)(Ch + (size_t)rbase * ldc + ccol) = __halves2bfloat162(h0, h1);
                *(__nv_bfloat162*)(Cl + (size_t)rbase * ldc + ccol) = __halves2bfloat162(l0, l1);
                split2(acc[mf][nf][2], h0, l0);
                split2(acc[mf][nf][3], h1, l1);
                *(__nv_bfloat162*)(Ch + (size_t)(rbase + 8) * ldc + ccol) = __halves2bfloat162(h0, h1);
                *(__nv_bfloat162*)(Cl + (size_t)(rbase + 8) * ldc + ccol) = __halves2bfloat162(l0, l1);
            }
        }
    }
}

// ---------------- prep kernels ----------------
__global__ void split_x_kernel(const float* __restrict__ x) {
    const int n = 8192 * 1024;
    for (int i = blockIdx.x * blockDim.x + threadIdx.x; i < n; i += gridDim.x * blockDim.x) {
        __nv_bfloat16 h, l;
        split2(x[i], h, l);
        g_xh[i] = h; g_xl[i] = l;
    }
}

__global__ void wt_kernel(const float* __restrict__ Wq, const float* __restrict__ Wk,
                          const float* __restrict__ Wv) {
    __shared__ float t[32][33];
    const float* W = (blockIdx.z == 0) ? Wq : (blockIdx.z == 1) ? Wk : Wv;
    __nv_bfloat16* Th = g_WTh + (size_t)blockIdx.z * 1024 * 1024;
    __nv_bfloat16* Tl = g_WTl + (size_t)blockIdx.z * 1024 * 1024;
    const int n0 = blockIdx.x * 32, k0 = blockIdx.y * 32;
    const int tx = threadIdx.x, ty = threadIdx.y;
#pragma unroll
    for (int i = 0; i < 4; ++i)
        t[ty + i * 8][tx] = W[(size_t)(k0 + ty + i * 8) * 1024 + n0 + tx];
    __syncthreads();
#pragma unroll
    for (int i = 0; i < 4; ++i) {
        __nv_bfloat16 h, l;
        split2(t[tx][ty + i * 8], h, l);  // = W[k0+tx][n0+ty+i*8]
        const size_t o = (size_t)(n0 + ty + i * 8) * 1024 + k0 + tx;
        Th[o] = h; Tl[o] = l;
    }
}

__global__ void vt_kernel() {
    __shared__ float t[32][33];
    const int b = blockIdx.z;
    const float* V = g_V + (size_t)b * 2048 * 1024;
    __nv_bfloat16* Th = g_VTh + (size_t)b * 1024 * 2048;
    __nv_bfloat16* Tl = g_VTl + (size_t)b * 1024 * 2048;
    const int e0 = blockIdx.x * 32, k0 = blockIdx.y * 32;
    const int tx = threadIdx.x, ty = threadIdx.y;
#pragma unroll
    for (int i = 0; i < 4; ++i)
        t[ty + i * 8][tx] = V[(size_t)(k0 + ty + i * 8) * 1024 + e0 + tx];
    __syncthreads();
#pragma unroll
    for (int i = 0; i < 4; ++i) {
        __nv_bfloat16 h, l;
        split2(t[tx][ty + i * 8], h, l);  // = V[k0+tx][e0+ty+i*8]
        const size_t o = (size_t)(e0 + ty + i * 8) * 2048 + k0 + tx;
        Th[o] = h; Tl[o] = l;
    }
}

// ---------------- GEMM kernels ----------------
__global__ void __launch_bounds__(TPB, 1)
proj_kernel() {
    const int z = blockIdx.z;
    const int m0 = blockIdx.y * 128;
    const int n0 = blockIdx.x * 128;
    const __nv_bfloat16* Bh = g_WTh + (size_t)z * 1024 * 1024;
    const __nv_bfloat16* Bl = g_WTl + (size_t)z * 1024 * 1024;
    if (z == 0)
        gemm_core<1>(g_xh, g_xl, 1024, Bh, Bl, 1024, m0, n0, 1024, 1.0f,
                     nullptr, g_Qh, g_Ql, 1024);
    else if (z == 1)
        gemm_core<1>(g_xh, g_xl, 1024, Bh, Bl, 1024, m0, n0, 1024, 1.0f,
                     nullptr, g_Kh, g_Kl, 1024);
    else
        gemm_core<0>(g_xh, g_xl, 1024, Bh, Bl, 1024, m0, n0, 1024, 1.0f,
                     g_V, nullptr, nullptr, 1024);
}

__global__ void __launch_bounds__(TPB, 1)
score_kernel() {
    const int kb = blockIdx.x, qb = blockIdx.y, b = blockIdx.z;
    if (kb > qb) return;
    const size_t qo = (size_t)b * 2048 * 1024;
    gemm_core<0>(g_Qh + qo, g_Ql + qo, 1024, g_Kh + qo, g_Kl + qo, 1024,
                 qb * 128, kb * 128, 1024, 0.03125f,
                 g_S + (size_t)b * 2048 * 2048, nullptr, nullptr, 2048);
}

__global__ void __launch_bounds__(TPB, 1)
pv_kernel(float* __restrict__ out) {
    const int nb = blockIdx.x, qb = blockIdx.y, b = blockIdx.z;
    const size_t po = (size_t)b * 2048 * 2048;
    const size_t vo = (size_t)b * 1024 * 2048;
    gemm_core<0>(g_Ph + po, g_Pl + po, 2048, g_VTh + vo, g_VTl + vo, 2048,
                 qb * 128, nb * 128, (qb + 1) * 128, 1.0f,
                 out + (size_t)b * 2048 * 1024, nullptr, nullptr, 1024);
}

// ---------------- softmax ----------------
__global__ void softmax_kernel() {
    const int q = blockIdx.x, b = blockIdx.y;
    float* row = g_S + ((size_t)b * 2048 + q) * 2048;
    __nv_bfloat16* ph = g_Ph + ((size_t)b * 2048 + q) * 2048;
    __nv_bfloat16* pl = g_Pl + ((size_t)b * 2048 + q) * 2048;
    const int len = q + 1;
    const int tid = threadIdx.x;
    __shared__ float red[TPB];

    float m = -1e30f;
    for (int i = tid; i < len; i += TPB) m = fmaxf(m, row[i]);
    red[tid] = m;
    __syncthreads();
#pragma unroll
    for (int s = TPB / 2; s > 0; s >>= 1) {
        if (tid < s) red[tid] = fmaxf(red[tid], red[tid + s]);
        __syncthreads();
    }
    m = red[0];
    __syncthreads();

    float sum = 0.0f;
    for (int i = tid; i < len; i += TPB) {
        float e = __expf(row[i] - m);
        row[i] = e;
        sum += e;
    }
    red[tid] = sum;
    __syncthreads();
#pragma unroll
    for (int s = TPB / 2; s > 0; s >>= 1) {
        if (tid < s) red[tid] += red[tid + s];
        __syncthreads();
    }
    const float inv = 1.0f / red[0];
    __syncthreads();

    const __nv_bfloat16 z = __float2bfloat16(0.0f);
    for (int i = tid; i < len; i += TPB) {
        __nv_bfloat16 h, l;
        split2(row[i] * inv, h, l);
        ph[i] = h; pl[i] = l;
    }
    const int klim = ((q >> 7) + 1) << 7;  // zero up to 128-tile boundary
    for (int i = len + tid; i < klim; i += TPB) { ph[i] = z; pl[i] = z; }
}

// ---------------- launch ----------------
extern "C" void kernel_launch(void* const* d_in, const int* in_sizes, int n_in,
                              void* d_out, int out_size) {
    const float* x  = (const float*)d_in[0];
    const float* Wq = (const float*)d_in[1];
    const float* Wk = (const float*)d_in[2];
    const float* Wv = (const float*)d_in[3];
    float* out = (float*)d_out;

    cudaFuncSetAttribute(proj_kernel,  cudaFuncAttributeMaxDynamicSharedMemorySize, GEMM_SMEM);
    cudaFuncSetAttribute(score_kernel, cudaFuncAttributeMaxDynamicSharedMemorySize, GEMM_SMEM);
    cudaFuncSetAttribute(pv_kernel,    cudaFuncAttributeMaxDynamicSharedMemorySize, GEMM_SMEM);

    split_x_kernel<<<4096, 256>>>(x);
    wt_kernel<<<dim3(32, 32, 3), dim3(32, 8)>>>(Wq, Wk, Wv);
    proj_kernel<<<dim3(8, 64, 3), TPB, GEMM_SMEM>>>();
    vt_kernel<<<dim3(32, 64, 4), dim3(32, 8)>>>();
    score_kernel<<<dim3(16, 16, 4), TPB, GEMM_SMEM>>>();
    softmax_kernel<<<dim3(2048, 4), TPB>>>();
    pv_kernel<<<dim3(8, 16, 4), TPB, GEMM_SMEM>>>(out);
}

// round 10
// speedup vs baseline: 1.9917x; 1.0012x over previous
#include <cuda_runtime.h>
#include <cuda_bf16.h>
#include <cstdint>

// CausalAttention via mma.sync bf16 hi/lo-split (3-MMA emulated fp32).
// tcgen05 is rejected by this harness's ptxas target (sm_103 baseline), so we
// use the sm_80 tensor-core ISA: mma.sync.m16n8k16 + ldmatrix + cp.async.
//
//  1) split_x    : x  -> xh, xl (bf16)
//  2) wt_kernel  : W{q,k,v} -> transposed hi/lo bf16 (W^T, K-contiguous)
//  3) proj_kernel: Q,K (split bf16 epilogue) and V (fp32) = x @ W
//  4) vt_kernel  : V -> V^T hi/lo bf16
//  5) score_kern : S = Q K^T / 32  (causal block skip), fp32
//  6) softmax    : row softmax -> Ph, Pl (bf16), zero tail to 128-boundary
//  7) pv_kernel  : out = P @ V  (fp32 epilogue, causal K limit)

typedef unsigned int u32;
typedef unsigned long long u64;

#define TPB 256
#define BK 64                 // K-chunk in bf16 elems
#define LDSS 72               // padded smem row (72 elems = 144B, conflict-free ldmatrix)
#define TILE_B (128 * LDSS * 2)          // 18432 B per 128x64 tile
#define BUF_B (4 * TILE_B)               // Ah, Al, Bh, Bl
#define GEMM_SMEM (2 * BUF_B)            // double buffer = 147456 B

// ---------------- scratch (no allocation anywhere) ----------------
__device__ __nv_bfloat16 g_xh[8192 * 1024];
__device__ __nv_bfloat16 g_xl[8192 * 1024];
__device__ __nv_bfloat16 g_WTh[3 * 1024 * 1024];
__device__ __nv_bfloat16 g_WTl[3 * 1024 * 1024];
__device__ __nv_bfloat16 g_Qh[4 * 2048 * 1024];
__device__ __nv_bfloat16 g_Ql[4 * 2048 * 1024];
__device__ __nv_bfloat16 g_Kh[4 * 2048 * 1024];
__device__ __nv_bfloat16 g_Kl[4 * 2048 * 1024];
__device__ float         g_V[4 * 2048 * 1024];
__device__ __nv_bfloat16 g_VTh[(size_t)4 * 1024 * 2048];
__device__ __nv_bfloat16 g_VTl[(size_t)4 * 1024 * 2048];
__device__ float         g_S[(size_t)4 * 2048 * 2048];
__device__ __nv_bfloat16 g_Ph[(size_t)4 * 2048 * 2048];
__device__ __nv_bfloat16 g_Pl[(size_t)4 * 2048 * 2048];

// ---------------- helpers ----------------
__device__ __forceinline__ u32 smem_u32(const void* p) {
    u32 a;
    asm("{ .reg .u64 t; cvta.to.shared.u64 t, %1; cvt.u32.u64 %0, t; }"
        : "=r"(a) : "l"(p));
    return a;
}

__device__ __forceinline__ void cp_async16(u32 dst, const void* src) {
    asm volatile("cp.async.cg.shared.global [%0], [%1], 16;"
                 :: "r"(dst), "l"(src) : "memory");
}
#define CP_COMMIT() asm volatile("cp.async.commit_group;" ::: "memory")
#define CP_WAIT(N)  asm volatile("cp.async.wait_group %0;" :: "n"(N) : "memory")

__device__ __forceinline__ void ldmx4(u32 a, u32& r0, u32& r1, u32& r2, u32& r3) {
    asm volatile("ldmatrix.sync.aligned.m8n8.x4.shared.b16 {%0,%1,%2,%3}, [%4];"
                 : "=r"(r0), "=r"(r1), "=r"(r2), "=r"(r3) : "r"(a));
}

__device__ __forceinline__ void mma16816(float c[4], const u32 a[4], const u32 b[2]) {
    asm volatile(
        "mma.sync.aligned.m16n8k16.row.col.f32.bf16.bf16.f32 "
        "{%0,%1,%2,%3}, {%4,%5,%6,%7}, {%8,%9}, {%0,%1,%2,%3};"
        : "+f"(c[0]), "+f"(c[1]), "+f"(c[2]), "+f"(c[3])
        : "r"(a[0]), "r"(a[1]), "r"(a[2]), "r"(a[3]), "r"(b[0]), "r"(b[1]));
}

__device__ __forceinline__ void split2(float v, __nv_bfloat16& h, __nv_bfloat16& l) {
    h = __float2bfloat16_rn(v);
    l = __float2bfloat16_rn(v - __bfloat162float(h));
}

// ---------------- GEMM core ----------------
// C[128x128 tile at (m0,n0)] = sum_k A[m,k]*B[n,k], A/B hi+lo bf16, K-major.
// MODE 0: fp32 out (Cf) * scale.   MODE 1: split bf16 out (Ch, Cl).
template <int MODE>
__device__ __forceinline__ void gemm_core(
    const __nv_bfloat16* __restrict__ Ah, const __nv_bfloat16* __restrict__ Al, int lda,
    const __nv_bfloat16* __restrict__ Bh, const __nv_bfloat16* __restrict__ Bl, int ldb,
    int m0, int n0, int Klen, float scale,
    float* __restrict__ Cf, __nv_bfloat16* __restrict__ Ch, __nv_bfloat16* __restrict__ Cl,
    int ldc)
{
    extern __shared__ char smem[];
    const u32 sbase = smem_u32(smem);
    const int tid = threadIdx.x;
    const int wid = tid >> 5;
    const int lane = tid & 31;
    const int warp_m = (wid & 3) * 32;   // 4 warps over M
    const int warp_n = (wid >> 2) * 64;  // 2 warps over N

    // cp.async mapping: 32 rows x 8 segs(16B) per pass, 4 passes per tile
    const int lrow = tid >> 3;            // 0..31
    const int lseg = (tid & 7) * 8;       // elem col 0..56
    const u32 dst_off = (u32)(lrow * LDSS + lseg) * 2;
    const __nv_bfloat16* pAh = Ah + (size_t)(m0 + lrow) * lda + lseg;
    const __nv_bfloat16* pAl = Al + (size_t)(m0 + lrow) * lda + lseg;
    const __nv_bfloat16* pBh = Bh + (size_t)(n0 + lrow) * ldb + lseg;
    const __nv_bfloat16* pBl = Bl + (size_t)(n0 + lrow) * ldb + lseg;

    const int nch = Klen / BK;

    // ldmatrix base offsets (within a tile)
    const u32 lm_a0 = (u32)((warp_m + (lane & 15)) * LDSS + (lane >> 4) * 8) * 2;
    const u32 lm_b0 = (u32)((warp_n + (lane & 15)) * LDSS + (lane >> 4) * 8) * 2;

    float acc[2][8][4];
#pragma unroll
    for (int i = 0; i < 2; ++i)
#pragma unroll
        for (int j = 0; j < 8; ++j)
#pragma unroll
            for (int q = 0; q < 4; ++q) acc[i][j][q] = 0.0f;

    // ---- prologue: load chunk 0 ----
    {
        const u32 ba = sbase;  // buffer 0
#pragma unroll
        for (int p = 0; p < 4; ++p) {
            const u32 d = ba + dst_off + (u32)(32 * p * LDSS) * 2;
            cp_async16(d + 0 * TILE_B, pAh + (size_t)(32 * p) * lda);
            cp_async16(d + 1 * TILE_B, pAl + (size_t)(32 * p) * lda);
            cp_async16(d + 2 * TILE_B, pBh + (size_t)(32 * p) * ldb);
            cp_async16(d + 3 * TILE_B, pBl + (size_t)(32 * p) * ldb);
        }
        CP_COMMIT();
    }

    for (int c = 0; c < nch; ++c) {
        // issue loads for chunk c+1 into the other buffer
        if (c + 1 < nch) {
            const u32 ba = sbase + ((c + 1) & 1) * BUF_B;
            const int k0 = (c + 1) * BK;
#pragma unroll
            for (int p = 0; p < 4; ++p) {
                const u32 d = ba + dst_off + (u32)(32 * p * LDSS) * 2;
                cp_async16(d + 0 * TILE_B, pAh + (size_t)(32 * p) * lda + k0);
                cp_async16(d + 1 * TILE_B, pAl + (size_t)(32 * p) * lda + k0);
                cp_async16(d + 2 * TILE_B, pBh + (size_t)(32 * p) * ldb + k0);
                cp_async16(d + 3 * TILE_B, pBl + (size_t)(32 * p) * ldb + k0);
            }
            CP_COMMIT();
            CP_WAIT(1);   // chunk c complete, c+1 in flight
        } else {
            CP_WAIT(0);
        }
        __syncthreads();

        const u32 ba = sbase + (c & 1) * BUF_B;
        const u32 aAh = ba + lm_a0;
        const u32 aAl = ba + TILE_B + lm_a0;
        const u32 aBh = ba + 2 * TILE_B + lm_b0;
        const u32 aBl = ba + 3 * TILE_B + lm_b0;

#pragma unroll
        for (int ks = 0; ks < BK / 16; ++ks) {
            const u32 ko = (u32)(ks * 16) * 2;
            u32 ah[2][4], al[2][4], bh[8][2], bl[8][2];
#pragma unroll
            for (int mf = 0; mf < 2; ++mf) {
                ldmx4(aAh + ko + (u32)(mf * 16 * LDSS) * 2,
                      ah[mf][0], ah[mf][1], ah[mf][2], ah[mf][3]);
                ldmx4(aAl + ko + (u32)(mf * 16 * LDSS) * 2,
                      al[mf][0], al[mf][1], al[mf][2], al[mf][3]);
            }
#pragma unroll
            for (int g = 0; g < 4; ++g) {   // 16 n-rows per ldmatrix.x4
                u32 r0, r1, r2, r3;
                ldmx4(aBh + ko + (u32)(g * 16 * LDSS) * 2, r0, r1, r2, r3);
                bh[2 * g][0] = r0; bh[2 * g][1] = r2;
                bh[2 * g + 1][0] = r1; bh[2 * g + 1][1] = r3;
                ldmx4(aBl + ko + (u32)(g * 16 * LDSS) * 2, r0, r1, r2, r3);
                bl[2 * g][0] = r0; bl[2 * g][1] = r2;
                bl[2 * g + 1][0] = r1; bl[2 * g + 1][1] = r3;
            }
#pragma unroll
            for (int mf = 0; mf < 2; ++mf)
#pragma unroll
                for (int nf = 0; nf < 8; ++nf) {
                    mma16816(acc[mf][nf], ah[mf], bh[nf]);
                    mma16816(acc[mf][nf], ah[mf], bl[nf]);
                    mma16816(acc[mf][nf], al[mf], bh[nf]);
                }
        }
        __syncthreads();
    }

    // ---- epilogue ----
    const int erow = lane >> 2;
    const int ecol = (lane & 3) * 2;
#pragma unroll
    for (int mf = 0; mf < 2; ++mf) {
        const int rbase = m0 + warp_m + mf * 16 + erow;
#pragma unroll
        for (int nf = 0; nf < 8; ++nf) {
            const int ccol = n0 + warp_n + nf * 8 + ecol;
            if (MODE == 0) {
                float2 v0, v1;
                v0.x = acc[mf][nf][0] * scale; v0.y = acc[mf][nf][1] * scale;
                v1.x = acc[mf][nf][2] * scale; v1.y = acc[mf][nf][3] * scale;
                *(float2*)(Cf + (size_t)rbase * ldc + ccol) = v0;
                *(float2*)(Cf + (size_t)(rbase + 8) * ldc + ccol) = v1;
            } else {
                __nv_bfloat16 h0, l0, h1, l1;
                split2(acc[mf][nf][0], h0, l0);
                split2(acc[mf][nf][1], h1, l1);
                *(__nv_bfloat162*)(Ch + (size_t)rbase * ldc + ccol) = __halves2bfloat162(h0, h1);
                *(__nv_bfloat162*)(Cl + (size_t)rbase * ldc + ccol) = __halves2bfloat162(l0, l1);
                split2(acc[mf][nf][2], h0, l0);
                split2(acc[mf][nf][3], h1, l1);
                *(__nv_bfloat162*)(Ch + (size_t)(rbase + 8) * ldc + ccol) = __halves2bfloat162(h0, h1);
                *(__nv_bfloat162*)(Cl + (size_t)(rbase + 8) * ldc + ccol) = __halves2bfloat162(l0, l1);
            }
        }
    }
}

// ---------------- prep kernels ----------------
__global__ void split_x_kernel(const float* __restrict__ x) {
    const int n = 8192 * 1024;
    for (int i = blockIdx.x * blockDim.x + threadIdx.x; i < n; i += gridDim.x * blockDim.x) {
        __nv_bfloat16 h, l;
        split2(x[i], h, l);
        g_xh[i] = h; g_xl[i] = l;
    }
}

__global__ void wt_kernel(const float* __restrict__ Wq, const float* __restrict__ Wk,
                          const float* __restrict__ Wv) {
    __shared__ float t[32][33];
    const float* W = (blockIdx.z == 0) ? Wq : (blockIdx.z == 1) ? Wk : Wv;
    __nv_bfloat16* Th = g_WTh + (size_t)blockIdx.z * 1024 * 1024;
    __nv_bfloat16* Tl = g_WTl + (size_t)blockIdx.z * 1024 * 1024;
    const int n0 = blockIdx.x * 32, k0 = blockIdx.y * 32;
    const int tx = threadIdx.x, ty = threadIdx.y;
#pragma unroll
    for (int i = 0; i < 4; ++i)
        t[ty + i * 8][tx] = W[(size_t)(k0 + ty + i * 8) * 1024 + n0 + tx];
    __syncthreads();
#pragma unroll
    for (int i = 0; i < 4; ++i) {
        __nv_bfloat16 h, l;
        split2(t[tx][ty + i * 8], h, l);  // = W[k0+tx][n0+ty+i*8]
        const size_t o = (size_t)(n0 + ty + i * 8) * 1024 + k0 + tx;
        Th[o] = h; Tl[o] = l;
    }
}

__global__ void vt_kernel() {
    __shared__ float t[32][33];
    const int b = blockIdx.z;
    const float* V = g_V + (size_t)b * 2048 * 1024;
    __nv_bfloat16* Th = g_VTh + (size_t)b * 1024 * 2048;
    __nv_bfloat16* Tl = g_VTl + (size_t)b * 1024 * 2048;
    const int e0 = blockIdx.x * 32, k0 = blockIdx.y * 32;
    const int tx = threadIdx.x, ty = threadIdx.y;
#pragma unroll
    for (int i = 0; i < 4; ++i)
        t[ty + i * 8][tx] = V[(size_t)(k0 + ty + i * 8) * 1024 + e0 + tx];
    __syncthreads();
#pragma unroll
    for (int i = 0; i < 4; ++i) {
        __nv_bfloat16 h, l;
        split2(t[tx][ty + i * 8], h, l);  // = V[k0+tx][e0+ty+i*8]
        const size_t o = (size_t)(e0 + ty + i * 8) * 2048 + k0 + tx;
        Th[o] = h; Tl[o] = l;
    }
}

// ---------------- GEMM kernels ----------------
__global__ void __launch_bounds__(TPB, 1)
proj_kernel() {
    const int z = blockIdx.z;
    const int m0 = blockIdx.y * 128;
    const int n0 = blockIdx.x * 128;
    const __nv_bfloat16* Bh = g_WTh + (size_t)z * 1024 * 1024;
    const __nv_bfloat16* Bl = g_WTl + (size_t)z * 1024 * 1024;
    if (z == 0)
        gemm_core<1>(g_xh, g_xl, 1024, Bh, Bl, 1024, m0, n0, 1024, 1.0f,
                     nullptr, g_Qh, g_Ql, 1024);
    else if (z == 1)
        gemm_core<1>(g_xh, g_xl, 1024, Bh, Bl, 1024, m0, n0, 1024, 1.0f,
                     nullptr, g_Kh, g_Kl, 1024);
    else
        gemm_core<0>(g_xh, g_xl, 1024, Bh, Bl, 1024, m0, n0, 1024, 1.0f,
                     g_V, nullptr, nullptr, 1024);
}

__global__ void __launch_bounds__(TPB, 1)
score_kernel() {
    const int kb = blockIdx.x, qb = blockIdx.y, b = blockIdx.z;
    if (kb > qb) return;
    const size_t qo = (size_t)b * 2048 * 1024;
    gemm_core<0>(g_Qh + qo, g_Ql + qo, 1024, g_Kh + qo, g_Kl + qo, 1024,
                 qb * 128, kb * 128, 1024, 0.03125f,
                 g_S + (size_t)b * 2048 * 2048, nullptr, nullptr, 2048);
}

__global__ void __launch_bounds__(TPB, 1)
pv_kernel(float* __restrict__ out) {
    const int nb = blockIdx.x, qb = blockIdx.y, b = blockIdx.z;
    const size_t po = (size_t)b * 2048 * 2048;
    const size_t vo = (size_t)b * 1024 * 2048;
    gemm_core<0>(g_Ph + po, g_Pl + po, 2048, g_VTh + vo, g_VTl + vo, 2048,
                 qb * 128, nb * 128, (qb + 1) * 128, 1.0f,
                 out + (size_t)b * 2048 * 1024, nullptr, nullptr, 1024);
}

// ---------------- softmax ----------------
__global__ void softmax_kernel() {
    const int q = blockIdx.x, b = blockIdx.y;
    float* row = g_S + ((size_t)b * 2048 + q) * 2048;
    __nv_bfloat16* ph = g_Ph + ((size_t)b * 2048 + q) * 2048;
    __nv_bfloat16* pl = g_Pl + ((size_t)b * 2048 + q) * 2048;
    const int len = q + 1;
    const int tid = threadIdx.x;
    __shared__ float red[TPB];

    float m = -1e30f;
    for (int i = tid; i < len; i += TPB) m = fmaxf(m, row[i]);
    red[tid] = m;
    __syncthreads();
#pragma unroll
    for (int s = TPB / 2; s > 0; s >>= 1) {
        if (tid < s) red[tid] = fmaxf(red[tid], red[tid + s]);
        __syncthreads();
    }
    m = red[0];
    __syncthreads();

    float sum = 0.0f;
    for (int i = tid; i < len; i += TPB) {
        float e = __expf(row[i] - m);
        row[i] = e;
        sum += e;
    }
    red[tid] = sum;
    __syncthreads();
#pragma unroll
    for (int s = TPB / 2; s > 0; s >>= 1) {
        if (tid < s) red[tid] += red[tid + s];
        __syncthreads();
    }
    const float inv = 1.0f / red[0];
    __syncthreads();

    const __nv_bfloat16 z = __float2bfloat16(0.0f);
    for (int i = tid; i < len; i += TPB) {
        __nv_bfloat16 h, l;
        split2(row[i] * inv, h, l);
        ph[i] = h; pl[i] = l;
    }
    const int klim = ((q >> 7) + 1) << 7;  // zero up to 128-tile boundary
    for (int i = len + tid; i < klim; i += TPB) { ph[i] = z; pl[i] = z; }
}

// ---------------- launch ----------------
extern "C" void kernel_launch(void* const* d_in, const int* in_sizes, int n_in,
                              void* d_out, int out_size) {
    const float* x  = (const float*)d_in[0];
    const float* Wq = (const float*)d_in[1];
    const float* Wk = (const float*)d_in[2];
    const float* Wv = (const float*)d_in[3];
    float* out = (float*)d_out;

    cudaFuncSetAttribute(proj_kernel,  cudaFuncAttributeMaxDynamicSharedMemorySize, GEMM_SMEM);
    cudaFuncSetAttribute(score_kernel, cudaFuncAttributeMaxDynamicSharedMemorySize, GEMM_SMEM);
    cudaFuncSetAttribute(pv_kernel,    cudaFuncAttributeMaxDynamicSharedMemorySize, GEMM_SMEM);

    split_x_kernel<<<4096, 256>>>(x);
    wt_kernel<<<dim3(32, 32, 3), dim3(32, 8)>>>(Wq, Wk, Wv);
    proj_kernel<<<dim3(8, 64, 3), TPB, GEMM_SMEM>>>();
    vt_kernel<<<dim3(32, 64, 4), dim3(32, 8)>>>();
    score_kernel<<<dim3(16, 16, 4), TPB, GEMM_SMEM>>>();
    softmax_kernel<<<dim3(2048, 4), TPB>>>();
    pv_kernel<<<dim3(8, 16, 4), TPB, GEMM_SMEM>>>(out);
}